// round 15
// baseline (speedup 1.0000x reference)
#include <cuda_runtime.h>
#include <cuda_bf16.h>
#include <cstdint>

// Problem constants
#define BB 8
#define SS 8192
#define DD 1024
#define NROWS (BB * SS)   // 65536 token rows
#define BINS 4096         // 12-bit buckets: sign + 8 exp + 3 mantissa bits
#define BSHIFT 20         // mono >> 20 -> 12-bit bucket
#define CAND_CAP 2048

// Scratch (allocation-free rule: __device__ globals). Zero at module load.
// Replay hygiene WITHOUT any cross-kernel protocol:
//   g_hist:   zeroed by the pivot block right after it reads it
//   g_rowcnt: reset to 0 by the pivot block (all adds for that row are done)
//   g_thresh: overwritten every call by the pivot before the map kernel reads it
//   g_scores: rewritten for every active token every call (mask is a fixed input)
__device__ float              g_scores[NROWS];
__device__ unsigned int       g_hist[BB * BINS];
__device__ unsigned int       g_rowcnt[BB];
__device__ unsigned long long g_thresh[BB];

__device__ __forceinline__ unsigned int mono_of(float s) {
    unsigned int bits = __float_as_uint(s);
    return (bits & 0x80000000u) ? ~bits : (bits | 0x80000000u);
}

// ---------------------------------------------------------------------------
// Kernel 1: scoring (2 rows/warp, active-only) + inline per-row pivot.
// Block = 256 threads = 8 warps = 16 consecutive token rows (never straddles
// a batch boundary: 8192 % 16 == 0). After a warp finishes its 2 rows it
// fences (orders its hist atomics + score stores) and adds 2 to the row
// counter. The block whose add completes the row (old == 8190) runs the
// pivot for that batch row after __syncthreads(). No waits anywhere.
// ---------------------------------------------------------------------------
__global__ __launch_bounds__(256) void score_kernel(
    const float4* __restrict__ hidden,        // NROWS * 256 float4
    const unsigned int* __restrict__ active,  // NROWS 32-bit bools
    const float4* __restrict__ w4,            // 256 float4
    const float*  __restrict__ bias)
{
    __shared__ int s_trig;
    __shared__ unsigned int s_wsum[8];
    __shared__ unsigned int s_woff[8];
    __shared__ int s_n;
    __shared__ int s_pivot;
    __shared__ unsigned int s_m;
    __shared__ int s_cnt;
    __shared__ unsigned long long s_th;
    __shared__ unsigned long long s_cand[CAND_CAP];   // 16 KB

    const int tid  = threadIdx.x;
    const int lane = tid & 31;
    const int wid  = tid >> 5;
    if (tid == 0) s_trig = 0;

    const int gwarp = blockIdx.x * 8 + wid;        // warp-task id
    const int r0 = gwarp * 2;
    const int r1 = r0 + 1;
    const int b  = blockIdx.x >> 9;                // batch row (512 blocks/batch)

    const unsigned int a0 = active[r0];
    const unsigned int a1 = active[r1];

    if ((a0 | a1) != 0u) {
        const float4* row0 = hidden + (size_t)r0 * (DD / 4);
        const float4* row1 = hidden + (size_t)r1 * (DD / 4);
        float acc0 = 0.f, acc1 = 0.f;

        if (a0 && a1) {
#pragma unroll
            for (int j = 0; j < 8; ++j) {
                float4 x0 = row0[lane + j * 32];
                float4 x1 = row1[lane + j * 32];
                float4 w  = w4[lane + j * 32];
                acc0 = fmaf(x0.x, w.x, acc0); acc1 = fmaf(x1.x, w.x, acc1);
                acc0 = fmaf(x0.y, w.y, acc0); acc1 = fmaf(x1.y, w.y, acc1);
                acc0 = fmaf(x0.z, w.z, acc0); acc1 = fmaf(x1.z, w.z, acc1);
                acc0 = fmaf(x0.w, w.w, acc0); acc1 = fmaf(x1.w, w.w, acc1);
            }
        } else {
            const float4* row = a0 ? row0 : row1;
            float acc = 0.f;
#pragma unroll
            for (int j = 0; j < 8; ++j) {
                float4 x = row[lane + j * 32];
                float4 w = w4[lane + j * 32];
                acc = fmaf(x.x, w.x, acc);
                acc = fmaf(x.y, w.y, acc);
                acc = fmaf(x.z, w.z, acc);
                acc = fmaf(x.w, w.w, acc);
            }
            if (a0) acc0 = acc; else acc1 = acc;
        }

        float b_val = *bias;
#pragma unroll
        for (int o = 16; o > 0; o >>= 1) {
            acc0 += __shfl_down_sync(0xffffffffu, acc0, o);
            acc1 += __shfl_down_sync(0xffffffffu, acc1, o);
        }

        if (lane == 0) {
            if (a0) {
                float s0 = acc0 + b_val;
                g_scores[r0] = s0;
                atomicAdd(&g_hist[b * BINS + (mono_of(s0) >> BSHIFT)], 1u);
            }
            if (a1) {
                float s1 = acc1 + b_val;
                g_scores[r1] = s1;
                atomicAdd(&g_hist[b * BINS + (mono_of(s1) >> BSHIFT)], 1u);
            }
            __threadfence();   // order hist atomics + score stores before count
        }
    }

    // count this warp's 2 rows (active or not); unique trigger on old==8190
    if (lane == 0) {
        unsigned int old = atomicAdd(&g_rowcnt[b], 2u);
        if (old == (unsigned)(SS - 2)) s_trig = 1;
    }
    __syncthreads();
    if (!s_trig) return;

    // =========== pivot for batch row b (whole block, 256 threads) ===========
    unsigned int* hist = g_hist + b * BINS;
    const float*        sc = g_scores + (size_t)b * SS;
    const unsigned int* am = active   + (size_t)b * SS;

    // chunk t covers bins [BINS-16(t+1), BINS-16t); ascending t == descending bins
    uint4 q[4];
    {
        uint4* hu4 = (uint4*)hist;
        int base_u4 = (BINS / 4) - 4 * (tid + 1);
#pragma unroll
        for (int j = 0; j < 4; ++j) {
            q[j] = hu4[base_u4 + j];
            hu4[base_u4 + j] = make_uint4(0u, 0u, 0u, 0u);   // self-reset
        }
    }
    unsigned int S = 0;
#pragma unroll
    for (int j = 0; j < 4; ++j) S += q[j].x + q[j].y + q[j].z + q[j].w;

    unsigned int inc = S;
#pragma unroll
    for (int o = 1; o < 32; o <<= 1) {
        unsigned int v = __shfl_up_sync(0xffffffffu, inc, o);
        if (lane >= o) inc += v;
    }
    if (lane == 31) s_wsum[wid] = inc;
    if (tid == 0) { s_cnt = 0; s_pivot = 0; s_m = 0u; }
    __syncthreads();
    if (tid == 0) {
        unsigned int run = 0;
#pragma unroll
        for (int wgi = 0; wgi < 8; ++wgi) { s_woff[wgi] = run; run += s_wsum[wgi]; }
        s_n = (int)run;
    }
    __syncthreads();
    inc += s_woff[wid];
    const unsigned int exc = inc - S;

    const int n_active = s_n;
    if (n_active == 0) {
        if (tid == 0) {
            g_thresh[b] = ~0ull;           // map kernel masks by act anyway
            atomicExch(&g_rowcnt[b], 0u);  // replay reset
        }
        return;
    }
    const unsigned int kk = (unsigned int)max(1, (n_active + 1) >> 1);

    if (exc < kk && kk <= inc) {           // exactly one thread owns the pivot
        const int bin_base = BINS - 16 * (tid + 1);
        unsigned int cum = exc;
        const unsigned int* qa = (const unsigned int*)q;   // 16 counts, ascending bins
        for (int j = 15; j >= 0; --j) {    // descending bins within chunk
            unsigned int cj = qa[j];
            if (cum + cj >= kk) { s_pivot = bin_base + j; s_m = kk - cum; break; }
            cum += cj;
        }
    }
    __syncthreads();
    const int pivot = s_pivot;
    const unsigned int m = s_m;

    // collect pivot-bucket candidates (32 iterations, L2-hot row)
    for (int i = tid; i < SS; i += 256) {
        if (am[i] != 0u) {
            unsigned int mono = mono_of(sc[i]);
            if ((int)(mono >> BSHIFT) == pivot) {
                int p = atomicAdd(&s_cnt, 1);
                if (p < CAND_CAP)
                    s_cand[p] = (((unsigned long long)mono) << 32)
                              | (unsigned long long)(0xFFFFFFFFu - (unsigned)i);
            }
        }
    }
    __syncthreads();

    // threshold = m-th largest candidate key (keys unique -> one winner)
    const int C = min(s_cnt, CAND_CAP);
    for (int c = tid; c < C; c += 256) {
        unsigned long long kc = s_cand[c];
        unsigned int rank = 0;
        for (int j = 0; j < C; ++j)
            rank += (s_cand[j] > kc);
        if (rank == m - 1)
            s_th = kc;
    }
    __syncthreads();
    if (tid == 0) {
        g_thresh[b] = s_th;                // visible at kernel boundary
        atomicExch(&g_rowcnt[b], 0u);      // replay reset (all adds are done)
    }
}

// ---------------------------------------------------------------------------
// Kernel 2: pure map — out = active && key >= thresh[batch]. No protocol.
// ---------------------------------------------------------------------------
__global__ __launch_bounds__(1024) void output_kernel(
    const unsigned int* __restrict__ active,
    float* __restrict__ out)
{
    int i = blockIdx.x * 1024 + threadIdx.x;   // 64 blocks x 1024 = NROWS
    unsigned int act = active[i];
    float s = g_scores[i];
    unsigned long long th = __ldg(&g_thresh[i >> 13]);
    unsigned long long key = (((unsigned long long)mono_of(s)) << 32)
                           | (unsigned long long)(0xFFFFFFFFu - (unsigned)(i & (SS - 1)));
    out[i] = (act != 0u && key >= th) ? 1.0f : 0.0f;
}

// ---------------------------------------------------------------------------
extern "C" void kernel_launch(void* const* d_in, const int* in_sizes, int n_in,
                              void* d_out, int out_size)
{
    const float4*       hidden = (const float4*)d_in[0];
    const unsigned int* mask   = (const unsigned int*)d_in[1];
    const float4*       w4     = (const float4*)d_in[2];
    const float*        bias   = (const float*)d_in[3];
    float*              out    = (float*)d_out;

    score_kernel<<<(NROWS / 2) / 8, 256>>>(hidden, mask, w4, bias);
    output_kernel<<<NROWS / 1024, 1024>>>(mask, out);
}

// round 16
// speedup vs baseline: 1.6034x; 1.6034x over previous
#include <cuda_runtime.h>
#include <cuda_bf16.h>
#include <cstdint>

// Problem constants
#define BB 8
#define SS 8192
#define DD 1024
#define NROWS (BB * SS)   // 65536 token rows
#define BINS 4096         // 12-bit buckets: sign + 8 exp + 3 mantissa bits
#define BSHIFT 20         // mono >> 20 -> 12-bit bucket
#define CAND_CAP 2048

// Scratch (allocation-free rule: __device__ globals). Zero at module load.
// g_hist is zeroed by select_kernel right after reading it -> clean replays.
// g_scores entries for inactive tokens are never consumed (mask guards them).
__device__ float        g_scores[NROWS];
__device__ unsigned int g_hist[BB * BINS];

__device__ __forceinline__ unsigned int mono_of(float s) {
    unsigned int bits = __float_as_uint(s);
    return (bits & 0x80000000u) ? ~bits : (bits | 0x80000000u);
}

// ---------------------------------------------------------------------------
// Kernel 1: scores for ACTIVE tokens only; TWO consecutive rows per warp to
// keep per-warp MLP high despite inactive-row early-outs. (R14 version —
// best measured; no completion counters, no fences.)
// ---------------------------------------------------------------------------
__global__ __launch_bounds__(256) void score_kernel(
    const float4* __restrict__ hidden,        // NROWS * 256 float4
    const unsigned int* __restrict__ active,  // NROWS 32-bit bools
    const float4* __restrict__ w4,            // 256 float4
    const float*  __restrict__ bias)
{
    int gwarp = (blockIdx.x * blockDim.x + threadIdx.x) >> 5;  // 0..NROWS/2-1
    int lane  = threadIdx.x & 31;

    const int r0 = gwarp * 2;
    const int r1 = r0 + 1;
    const unsigned int a0 = active[r0];
    const unsigned int a1 = active[r1];
    if ((a0 | a1) == 0u) return;

    const float4* row0 = hidden + (size_t)r0 * (DD / 4);
    const float4* row1 = hidden + (size_t)r1 * (DD / 4);

    float acc0 = 0.f, acc1 = 0.f;

    if (a0 && a1) {
#pragma unroll
        for (int j = 0; j < 8; ++j) {
            float4 x0 = row0[lane + j * 32];
            float4 x1 = row1[lane + j * 32];
            float4 w  = w4[lane + j * 32];
            acc0 = fmaf(x0.x, w.x, acc0); acc1 = fmaf(x1.x, w.x, acc1);
            acc0 = fmaf(x0.y, w.y, acc0); acc1 = fmaf(x1.y, w.y, acc1);
            acc0 = fmaf(x0.z, w.z, acc0); acc1 = fmaf(x1.z, w.z, acc1);
            acc0 = fmaf(x0.w, w.w, acc0); acc1 = fmaf(x1.w, w.w, acc1);
        }
    } else {
        const float4* row = a0 ? row0 : row1;
        float acc = 0.f;
#pragma unroll
        for (int j = 0; j < 8; ++j) {
            float4 x = row[lane + j * 32];
            float4 w = w4[lane + j * 32];
            acc = fmaf(x.x, w.x, acc);
            acc = fmaf(x.y, w.y, acc);
            acc = fmaf(x.z, w.z, acc);
            acc = fmaf(x.w, w.w, acc);
        }
        if (a0) acc0 = acc; else acc1 = acc;
    }

    float b_val = *bias;

#pragma unroll
    for (int o = 16; o > 0; o >>= 1) {
        acc0 += __shfl_down_sync(0xffffffffu, acc0, o);
        acc1 += __shfl_down_sync(0xffffffffu, acc1, o);
    }

    if (lane == 0) {
        int b = r0 >> 13;
        if (a0) {
            float s0 = acc0 + b_val;
            g_scores[r0] = s0;
            atomicAdd(&g_hist[b * BINS + (mono_of(s0) >> BSHIFT)], 1u);
        }
        if (a1) {
            float s1 = acc1 + b_val;
            g_scores[r1] = s1;
            atomicAdd(&g_hist[b * BINS + (mono_of(s1) >> BSHIFT)], 1u);
        }
    }
}

// ---------------------------------------------------------------------------
// Kernel 2 (grid=8, 1024 threads, ONE CTA per batch row, NO inter-CTA sync):
//   preload 8 tokens/thread with wide loads (2x uint4 mask + 2x float4 score)
//   hist read+zero (1 uint4/thread) -> block suffix scan -> (pivot, m)
//   candidates filtered from REGISTERS into smem; rank in smem (keys unique)
//   outputs assembled in registers, stored as 2x float4 (fully coalesced)
// ---------------------------------------------------------------------------
__global__ __launch_bounds__(1024) void select_kernel(
    const unsigned int* __restrict__ active,  // [BB, SS]
    float* __restrict__ out)                  // [BB, SS] bool as float32
{
    __shared__ unsigned int warp_sums[32];
    __shared__ int s_n;
    __shared__ int s_pivot;
    __shared__ unsigned int s_m;
    __shared__ int s_cnt;
    __shared__ unsigned long long s_cand[CAND_CAP];   // 16 KB

    const int row  = blockIdx.x;
    const int tid  = threadIdx.x;
    const int lane = tid & 31;
    const int wid  = tid >> 5;

    const unsigned int* am = active   + (size_t)row * SS;
    const float*        sc = g_scores + (size_t)row * SS;
    float*              op = out      + (size_t)row * SS;

    // ---- preload this thread's 8 tokens (base = tid*8) ----
    const int base = tid * 8;
    uint4  m0 = ((const uint4*) am)[2 * tid];
    uint4  m1 = ((const uint4*) am)[2 * tid + 1];
    float4 v0 = ((const float4*)sc)[2 * tid];
    float4 v1 = ((const float4*)sc)[2 * tid + 1];

    unsigned int actv[8] = { m0.x, m0.y, m0.z, m0.w, m1.x, m1.y, m1.z, m1.w };
    float        sval[8] = { v0.x, v0.y, v0.z, v0.w, v1.x, v1.y, v1.z, v1.w };
    unsigned int mono[8];
#pragma unroll
    for (int j = 0; j < 8; ++j) mono[j] = mono_of(sval[j]);

    // ---- histogram read + self-reset + suffix scan -> (pivot, m) ----
    unsigned int* hist = g_hist + row * BINS;

    uint4 h = ((const uint4*)hist)[1023 - tid];
    ((uint4*)hist)[1023 - tid] = make_uint4(0u, 0u, 0u, 0u);
    unsigned int S = h.x + h.y + h.z + h.w;

    unsigned int inc = S;
#pragma unroll
    for (int o = 1; o < 32; o <<= 1) {
        unsigned int v = __shfl_up_sync(0xffffffffu, inc, o);
        if (lane >= o) inc += v;
    }
    if (lane == 31) warp_sums[wid] = inc;
    if (tid == 0) { s_cnt = 0; s_pivot = 0; s_m = 0u; }
    __syncthreads();
    if (wid == 0) {
        unsigned int w = warp_sums[lane];
        unsigned int wi = w;
#pragma unroll
        for (int o = 1; o < 32; o <<= 1) {
            unsigned int v = __shfl_up_sync(0xffffffffu, wi, o);
            if (lane >= o) wi += v;
        }
        warp_sums[lane] = wi - w;
        if (lane == 31) s_n = (int)wi;
    }
    __syncthreads();
    inc += warp_sums[wid];
    const unsigned int exc = inc - S;

    const int n_active = s_n;
    if (n_active == 0) {
        float4 z = make_float4(0.f, 0.f, 0.f, 0.f);
        ((float4*)op)[2 * tid]     = z;
        ((float4*)op)[2 * tid + 1] = z;
        return;
    }
    const unsigned int kk = (unsigned int)max(1, (n_active + 1) >> 1);

    if (exc < kk && kk <= inc) {   // exactly one thread owns the pivot
        int bin_base = (1023 - tid) * 4;
        unsigned int cum = exc;
        unsigned int v[4] = { h.w, h.z, h.y, h.x };   // descending bins
#pragma unroll
        for (int j = 0; j < 4; ++j) {
            if (cum + v[j] >= kk) { s_pivot = bin_base + 3 - j; s_m = kk - cum; break; }
            cum += v[j];
        }
    }
    __syncthreads();
    const int pivot = s_pivot;
    const unsigned int m = s_m;

    // ---- push pivot-bucket candidates from registers into smem ----
    int bkt[8];
    bool cnd[8];
#pragma unroll
    for (int j = 0; j < 8; ++j) {
        bkt[j] = (int)(mono[j] >> BSHIFT);
        cnd[j] = (actv[j] != 0u) && (bkt[j] == pivot);
        if (cnd[j]) {
            int p = atomicAdd(&s_cnt, 1);
            if (p < CAND_CAP)
                s_cand[p] = (((unsigned long long)mono[j]) << 32)
                          | (unsigned long long)(0xFFFFFFFFu - (unsigned)(base + j));
        }
    }
    __syncthreads();
    const int C = min(s_cnt, CAND_CAP);

    // ---- decide all 8 tokens; rank own candidates against smem list ----
    float r[8];
#pragma unroll
    for (int j = 0; j < 8; ++j) {
        if (actv[j] == 0u) { r[j] = 0.0f; continue; }
        if (bkt[j] > pivot) { r[j] = 1.0f; continue; }
        if (!cnd[j])        { r[j] = 0.0f; continue; }
        unsigned long long key = (((unsigned long long)mono[j]) << 32)
                               | (unsigned long long)(0xFFFFFFFFu - (unsigned)(base + j));
        unsigned int rank = 0;
        for (int q = 0; q < C; ++q)
            rank += (s_cand[q] > key);
        r[j] = (rank < m) ? 1.0f : 0.0f;
    }

    // ---- coalesced wide stores ----
    ((float4*)op)[2 * tid]     = make_float4(r[0], r[1], r[2], r[3]);
    ((float4*)op)[2 * tid + 1] = make_float4(r[4], r[5], r[6], r[7]);
}

// ---------------------------------------------------------------------------
extern "C" void kernel_launch(void* const* d_in, const int* in_sizes, int n_in,
                              void* d_out, int out_size)
{
    const float4*       hidden = (const float4*)d_in[0];
    const unsigned int* mask   = (const unsigned int*)d_in[1];
    const float4*       w4     = (const float4*)d_in[2];
    const float*        bias   = (const float*)d_in[3];
    float*              out    = (float*)d_out;

    score_kernel<<<(NROWS / 2) / 8, 256>>>(hidden, mask, w4, bias);
    select_kernel<<<BB, 1024>>>(mask, out);
}